// round 1
// baseline (speedup 1.0000x reference)
#include <cuda_runtime.h>
#include <math.h>

#define Bz 2
#define Tz 1024
#define Cz 1024
#define Hz 16
#define HSz 64

// ---------------- scratch (static device arrays; no allocations) ----------------
__device__ float g_xs[Bz * Tz * Cz];
__device__ float g_q [Bz * Tz * Cz];
__device__ float g_k [Bz * Tz * Cz];
__device__ float g_v [Bz * Tz * Cz];
__device__ float g_y [Bz * Tz * Cz];
__device__ float g_S [(size_t)Bz * Hz * Tz * Tz];   // scores -> softmax*w (in place)
__device__ float g_M2[(size_t)Bz * Hz * Tz * Tz];   // head-mixed attention

// ---------------- 1. time shift: xs[:, t, :512] = x[:, t-1, :512] ----------------
__global__ __launch_bounds__(256) void shift_kernel(const float* __restrict__ x,
                                                    float* __restrict__ xs) {
    int idx = blockIdx.x * 256 + threadIdx.x;            // B*T*C elements
    int c = idx & (Cz - 1);
    int t = (idx >> 10) & (Tz - 1);
    float val;
    if (c < Cz / 2)
        val = (t == 0) ? 0.f : x[idx - Cz];
    else
        val = x[idx];
    xs[idx] = val;
}

// ---------------- 2/8. tiled SGEMM 128x128x8, 256 threads, 8x8 per thread -------
// MODE 0: C[((b*H+h)*T+t)*HS+d] = acc + bias[c]      (QKV transpose epilogue)
// MODE 1: C[r*N+c] = (acc + bias[c]) * gamma[t]      (output epilogue)
template <int MODE>
__global__ __launch_bounds__(256) void sgemm128(const float* __restrict__ A,
                                                const float* __restrict__ Bm,
                                                const float* __restrict__ bias,
                                                float* __restrict__ Cout,
                                                const float* __restrict__ gamma,
                                                int M, int N, int K) {
    __shared__ float As[8][128];
    __shared__ float Bs[8][128];
    int tid = threadIdx.x;
    int bm = blockIdx.y * 128;
    int bn = blockIdx.x * 128;

    int arow = tid >> 1;            // 0..127
    int acol = (tid & 1) * 4;       // 0 or 4
    int brow = tid >> 5;            // 0..7
    int bcol = (tid & 31) * 4;      // 0..124

    int ty = tid >> 4, tx = tid & 15;

    float acc[8][8];
#pragma unroll
    for (int i = 0; i < 8; i++)
#pragma unroll
        for (int j = 0; j < 8; j++) acc[i][j] = 0.f;

    for (int k0 = 0; k0 < K; k0 += 8) {
        float4 a4 = *(const float4*)(A + (size_t)(bm + arow) * K + k0 + acol);
        As[acol + 0][arow] = a4.x;
        As[acol + 1][arow] = a4.y;
        As[acol + 2][arow] = a4.z;
        As[acol + 3][arow] = a4.w;
        float4 b4 = *(const float4*)(Bm + (size_t)(k0 + brow) * N + bn + bcol);
        *(float4*)&Bs[brow][bcol] = b4;
        __syncthreads();

#pragma unroll
        for (int kk = 0; kk < 8; kk++) {
            float ar[8], br[8];
            *(float4*)&ar[0] = *(float4*)&As[kk][ty * 8];
            *(float4*)&ar[4] = *(float4*)&As[kk][ty * 8 + 4];
            *(float4*)&br[0] = *(float4*)&Bs[kk][tx * 8];
            *(float4*)&br[4] = *(float4*)&Bs[kk][tx * 8 + 4];
#pragma unroll
            for (int i = 0; i < 8; i++)
#pragma unroll
                for (int j = 0; j < 8; j++) acc[i][j] += ar[i] * br[j];
        }
        __syncthreads();
    }

#pragma unroll
    for (int i = 0; i < 8; i++) {
        int r = bm + ty * 8 + i;
        int b = r >> 10;
        int t = r & (Tz - 1);
        float gm = 1.f;
        if (MODE == 1) gm = gamma[t];
#pragma unroll
        for (int j = 0; j < 8; j++) {
            int c = bn + tx * 8 + j;
            float val = acc[i][j] + bias[c];
            if (MODE == 0) {
                int h = c >> 6, d = c & 63;
                Cout[(((size_t)b * Hz + h) * Tz + t) * HSz + d] = val;
            } else {
                Cout[(size_t)r * N + c] = val * gm;
            }
        }
    }
}

// ---------------- 3. RoPE on first 32 dims of each head (q and k) ---------------
__global__ __launch_bounds__(256) void rope_kernel(float* __restrict__ q,
                                                   float* __restrict__ k) {
    int idx = blockIdx.x * 256 + threadIdx.x;   // B*H*T*16 pairs
    int j  = idx & 15;
    int t  = (idx >> 4) & (Tz - 1);
    int bh = idx >> 14;
    double freq = pow(1024.0, -(double)j / 16.0);
    double ang  = (double)t * freq;
    float c = (float)cos(ang);
    float s = (float)sin(ang);
    size_t base = ((size_t)bh * Tz + t) * HSz + j;
    float q0 = q[base], q1 = q[base + 16];
    q[base]      = q0 * c - q1 * s;
    q[base + 16] = q1 * c + q0 * s;
    float k0 = k[base], k1 = k[base + 16];
    k[base]      = k0 * c - k1 * s;
    k[base + 16] = k1 * c + k0 * s;
}

// ---------------- 4. scores: S = q @ k^T * 1/sqrt(HS), batched over (b,h) ------
__global__ __launch_bounds__(256) void scores_kernel(const float* __restrict__ q,
                                                     const float* __restrict__ k,
                                                     float* __restrict__ S) {
    __shared__ float Qs[64][68];   // [d][t]
    __shared__ float Ks[64][68];   // [d][s]
    int bh = blockIdx.z;
    int t0 = blockIdx.y * 64, s0 = blockIdx.x * 64;
    int tid = threadIdx.x;

    for (int i = tid; i < 64 * 16; i += 256) {
        int row = i >> 4;
        int c4 = (i & 15) * 4;
        float4 a = *(const float4*)(q + ((size_t)bh * Tz + t0 + row) * HSz + c4);
        Qs[c4 + 0][row] = a.x; Qs[c4 + 1][row] = a.y;
        Qs[c4 + 2][row] = a.z; Qs[c4 + 3][row] = a.w;
        float4 b4 = *(const float4*)(k + ((size_t)bh * Tz + s0 + row) * HSz + c4);
        Ks[c4 + 0][row] = b4.x; Ks[c4 + 1][row] = b4.y;
        Ks[c4 + 2][row] = b4.z; Ks[c4 + 3][row] = b4.w;
    }
    __syncthreads();

    int ty = tid >> 4, tx = tid & 15;
    float acc[4][4];
#pragma unroll
    for (int i = 0; i < 4; i++)
#pragma unroll
        for (int j = 0; j < 4; j++) acc[i][j] = 0.f;

#pragma unroll 4
    for (int d = 0; d < 64; d++) {
        float4 qv = *(float4*)&Qs[d][ty * 4];
        float4 kv = *(float4*)&Ks[d][tx * 4];
        float qa[4] = {qv.x, qv.y, qv.z, qv.w};
        float ka[4] = {kv.x, kv.y, kv.z, kv.w};
#pragma unroll
        for (int i = 0; i < 4; i++)
#pragma unroll
            for (int j = 0; j < 4; j++) acc[i][j] += qa[i] * ka[j];
    }

#pragma unroll
    for (int i = 0; i < 4; i++)
#pragma unroll
        for (int j = 0; j < 4; j++)
            S[((size_t)bh * Tz + t0 + ty * 4 + i) * Tz + s0 + tx * 4 + j] =
                acc[i][j] * 0.125f;
}

// ---------------- 5. softmax over full row (no mask), then * w[h,t,s] -----------
__global__ __launch_bounds__(256) void softmax_w_kernel(float* __restrict__ S,
                                                        const float* __restrict__ tw,
                                                        const float* __restrict__ alpha,
                                                        const float* __restrict__ beta) {
    int row_id = blockIdx.x;                    // (b*H + h)*T + t
    int t = row_id & (Tz - 1);
    int h = (row_id >> 10) & (Hz - 1);
    float* row = S + (size_t)row_id * Tz;
    int tid = threadIdx.x;

    float4 vv = *(float4*)(row + tid * 4);
    float m = fmaxf(fmaxf(vv.x, vv.y), fmaxf(vv.z, vv.w));
#pragma unroll
    for (int o = 16; o; o >>= 1) m = fmaxf(m, __shfl_xor_sync(0xffffffffu, m, o));
    __shared__ float redm[8];
    __shared__ float reds[8];
    if ((tid & 31) == 0) redm[tid >> 5] = m;
    __syncthreads();
    float bm = redm[0];
#pragma unroll
    for (int i = 1; i < 8; i++) bm = fmaxf(bm, redm[i]);

    float e0 = expf(vv.x - bm), e1 = expf(vv.y - bm);
    float e2 = expf(vv.z - bm), e3 = expf(vv.w - bm);
    float s = e0 + e1 + e2 + e3;
#pragma unroll
    for (int o = 16; o; o >>= 1) s += __shfl_xor_sync(0xffffffffu, s, o);
    if ((tid & 31) == 0) reds[tid >> 5] = s;
    __syncthreads();
    float bs = 0.f;
#pragma unroll
    for (int i = 0; i < 8; i++) bs += reds[i];
    float inv = 1.f / bs;

    float bt = beta[h * Tz + t];
    float e[4] = {e0, e1, e2, e3};
    float4 outv;
    float* op = &outv.x;
#pragma unroll
    for (int l = 0; l < 4; l++) {
        int sidx = tid * 4 + l;
        float w = 0.f;
        if (sidx <= t)
            w = tw[h * Tz + 1023 + sidx - t] * alpha[h * Tz + sidx] * bt;
        op[l] = e[l] * inv * w;
    }
    *(float4*)(row + tid * 4) = outv;
}

// ---------------- 6. head mix: M2[b,g,t,s] = sum_h Wmix[g,h]*A[b,h,t,s] ---------
__global__ __launch_bounds__(256) void mix_kernel(const float* __restrict__ A,
                                                  float* __restrict__ M2,
                                                  const float* __restrict__ Wmix) {
    __shared__ float wm[256];
    int tid = threadIdx.x;
    wm[tid] = Wmix[tid];
    __syncthreads();
    int s = blockIdx.x * 256 + tid;
    int t = blockIdx.y;
    int b = blockIdx.z;
    float vals[16];
#pragma unroll
    for (int h = 0; h < 16; h++)
        vals[h] = A[(((size_t)b * Hz + h) * Tz + t) * Tz + s];
#pragma unroll
    for (int g = 0; g < 16; g++) {
        float a = 0.f;
#pragma unroll
        for (int h = 0; h < 16; h++) a += wm[g * 16 + h] * vals[h];
        M2[(((size_t)b * Hz + g) * Tz + t) * Tz + s] = a;
    }
}

// ---------------- 7. PV: y[b,t, g*64+d] = sum_s M2[b,g,t,s]*v[b,g,s,d] ----------
__global__ __launch_bounds__(256) void pv_kernel(const float* __restrict__ M2,
                                                 const float* __restrict__ v,
                                                 float* __restrict__ y) {
    __shared__ float Ps[64][68];   // [s][t]
    __shared__ float Vs[64][68];   // [s][d]
    int bg = blockIdx.y;
    int b = bg >> 4, g = bg & 15;
    int t0 = blockIdx.x * 64;
    int tid = threadIdx.x;
    int ty = tid >> 4, tx = tid & 15;

    float acc[4][4];
#pragma unroll
    for (int i = 0; i < 4; i++)
#pragma unroll
        for (int j = 0; j < 4; j++) acc[i][j] = 0.f;

    for (int s0 = 0; s0 < Tz; s0 += 64) {
        for (int i = tid; i < 64 * 16; i += 256) {
            int row = i >> 4;
            int c4 = (i & 15) * 4;
            float4 a = *(const float4*)(M2 + ((size_t)bg * Tz + t0 + row) * Tz + s0 + c4);
            Ps[c4 + 0][row] = a.x; Ps[c4 + 1][row] = a.y;
            Ps[c4 + 2][row] = a.z; Ps[c4 + 3][row] = a.w;
            float4 b4 = *(const float4*)(v + ((size_t)bg * Tz + s0 + row) * HSz + c4);
            *(float4*)&Vs[row][c4] = b4;
        }
        __syncthreads();
#pragma unroll 4
        for (int s = 0; s < 64; s++) {
            float4 pv = *(float4*)&Ps[s][ty * 4];
            float4 vv = *(float4*)&Vs[s][tx * 4];
            float pa[4] = {pv.x, pv.y, pv.z, pv.w};
            float va[4] = {vv.x, vv.y, vv.z, vv.w};
#pragma unroll
            for (int i = 0; i < 4; i++)
#pragma unroll
                for (int j = 0; j < 4; j++) acc[i][j] += pa[i] * va[j];
        }
        __syncthreads();
    }

#pragma unroll
    for (int i = 0; i < 4; i++)
#pragma unroll
        for (int j = 0; j < 4; j++)
            y[((size_t)b * Tz + t0 + ty * 4 + i) * Cz + g * HSz + tx * 4 + j] = acc[i][j];
}

// ---------------- launch ----------------
extern "C" void kernel_launch(void* const* d_in, const int* in_sizes, int n_in,
                              void* d_out, int out_size) {
    const float* x          = (const float*)d_in[0];
    const float* time_w     = (const float*)d_in[1];
    const float* time_alpha = (const float*)d_in[2];
    const float* time_beta  = (const float*)d_in[3];
    const float* time_gamma = (const float*)d_in[4];
    const float* Wq = (const float*)d_in[5];
    const float* bq = (const float*)d_in[6];
    const float* Wk = (const float*)d_in[7];
    const float* bk = (const float*)d_in[8];
    const float* Wv = (const float*)d_in[9];
    const float* bv = (const float*)d_in[10];
    const float* Wmix = (const float*)d_in[11];
    const float* Wo = (const float*)d_in[12];
    const float* bo = (const float*)d_in[13];
    float* out = (float*)d_out;

    float *xs, *q, *k, *v, *y, *S, *M2;
    cudaGetSymbolAddress((void**)&xs, g_xs);
    cudaGetSymbolAddress((void**)&q,  g_q);
    cudaGetSymbolAddress((void**)&k,  g_k);
    cudaGetSymbolAddress((void**)&v,  g_v);
    cudaGetSymbolAddress((void**)&y,  g_y);
    cudaGetSymbolAddress((void**)&S,  g_S);
    cudaGetSymbolAddress((void**)&M2, g_M2);

    const int M = Bz * Tz, N = Cz, K = Cz;

    shift_kernel<<<(Bz * Tz * Cz) / 256, 256>>>(x, xs);

    dim3 gGemm(N / 128, M / 128);
    sgemm128<0><<<gGemm, 256>>>(xs, Wq, bq, q, nullptr, M, N, K);
    sgemm128<0><<<gGemm, 256>>>(xs, Wk, bk, k, nullptr, M, N, K);
    sgemm128<0><<<gGemm, 256>>>(xs, Wv, bv, v, nullptr, M, N, K);

    rope_kernel<<<(Bz * Hz * Tz * 16) / 256, 256>>>(q, k);

    dim3 gScores(Tz / 64, Tz / 64, Bz * Hz);
    scores_kernel<<<gScores, 256>>>(q, k, S);

    softmax_w_kernel<<<Bz * Hz * Tz, 256>>>(S, time_w, time_alpha, time_beta);

    mix_kernel<<<dim3(Tz / 256, Tz, Bz), 256>>>(S, M2, Wmix);

    pv_kernel<<<dim3(Tz / 64, Bz * Hz), 256>>>(M2, v, y);

    sgemm128<1><<<gGemm, 256>>>(y, Wo, bo, out, time_gamma, M, N, K);
}

// round 2
// speedup vs baseline: 2.2421x; 2.2421x over previous
#include <cuda_runtime.h>
#include <math.h>

#define Bz 2
#define Tz 1024
#define Cz 1024
#define Hz 16
#define HSz 64

// ---------------- scratch ----------------
__device__ float g_xs[Bz * Tz * Cz];
__device__ float g_q [Bz * Tz * Cz];
__device__ float g_k [Bz * Tz * Cz];
__device__ float g_v [Bz * Tz * Cz];
__device__ float g_kt[Bz * Tz * Cz];
__device__ float g_y [Bz * Tz * Cz];
__device__ float g_S [(size_t)Bz * Hz * Tz * Tz];
__device__ float g_M2[(size_t)Bz * Hz * Tz * Tz];

__device__ __forceinline__ float t32(float x) {
    unsigned u;
    asm("cvt.rna.tf32.f32 %0, %1;" : "=r"(u) : "f"(x));
    return __uint_as_float(u);
}
__device__ __forceinline__ unsigned fu(float x) { return __float_as_uint(x); }

// ---------------- 1. time shift ----------------
__global__ __launch_bounds__(256) void shift_kernel(const float* __restrict__ x,
                                                    float* __restrict__ xs) {
    int idx = blockIdx.x * 256 + threadIdx.x;
    int c = idx & (Cz - 1);
    int t = (idx >> 10) & (Tz - 1);
    float val;
    if (c < Cz / 2)
        val = (t == 0) ? 0.f : x[idx - Cz];
    else
        val = x[idx];
    xs[idx] = val;
}

// ---------------- generic tf32 tensor-core GEMM ----------------
// MODE 0: fused QKV  (A=xs 2048x1024, logical N=3072, scatter to [b,h,t,d] + bias)
// MODE 1: output     (A=y 2048x1024, N=1024, (acc+bias)*gamma[t])
// MODE 2: scores     (batched bh: A=q[bh] 1024x64, B=kt[bh] 64x1024, *0.125)
// MODE 3: PV         (batched bg: A=M2[bg] 1024x1024, B=v[bg] 1024x64 -> y[b,t,g*64+d])
template <int MODE, int TN, int KD, int LDA, int LDB>
__global__ __launch_bounds__(256) void gemm_tf32(
    const float* __restrict__ A0,
    const float* __restrict__ B0, const float* __restrict__ B1, const float* __restrict__ B2,
    const float* __restrict__ bias0, const float* __restrict__ bias1, const float* __restrict__ bias2,
    float* __restrict__ O0, float* __restrict__ O1, float* __restrict__ O2,
    const float* __restrict__ gamma)
{
    constexpr int PA = 133;           // padded As row (scalar access, conflict-free stores)
    constexpr int PB = TN + 4;        // padded Bs row (float4 stores aligned)
    constexpr int NB = (TN == 128) ? 4 : 2;
    constexpr int WNT = TN / 4;       // warp n extent (32 or 16)
    constexpr int NT = WNT / 8;       // n-tiles per warp (4 or 2)
    constexpr int PANELS = KD / 32;

    extern __shared__ float sh[];
    float* AsBase = sh;                  // [2][32][PA]
    float* BsBase = sh + 2 * 32 * PA;    // [2][32][PB]

    int tid = threadIdx.x;
    int lane = tid & 31, wid = tid >> 5;
    int wm = wid >> 2, wn = wid & 3;     // 2 x 4 warp grid
    int z = blockIdx.z;
    int bm = blockIdx.y * 128;
    int bnL = blockIdx.x * TN;

    const float* Ab = A0;
    const float* Bb = B0;
    const float* bias = bias0;
    float* Out = O0;
    int bn = bnL;
    if constexpr (MODE == 0) {
        int which = bnL >> 10;
        bn = bnL & 1023;
        Bb   = which == 0 ? B0 : (which == 1 ? B1 : B2);
        bias = which == 0 ? bias0 : (which == 1 ? bias1 : bias2);
        Out  = which == 0 ? O0 : (which == 1 ? O1 : O2);
    } else if constexpr (MODE == 2) {
        Ab = A0 + (size_t)z * Tz * HSz;
        Bb = B0 + (size_t)z * Tz * HSz;
    } else if constexpr (MODE == 3) {
        Ab = A0 + (size_t)z * Tz * Tz;
        Bb = B0 + (size_t)z * Tz * HSz;
    }

    float4 va[4], vb[NB];

    auto loadA = [&](int p) {
#pragma unroll
        for (int j = 0; j < 4; j++) {
            int idx = tid + j * 256;
            int row = idx >> 3, kc = idx & 7;
            va[j] = *(const float4*)(Ab + (size_t)(bm + row) * LDA + p * 32 + kc * 4);
        }
    };
    auto loadB = [&](int p) {
#pragma unroll
        for (int j = 0; j < NB; j++) {
            int idx = tid + j * 256;
            int krow = (TN == 128) ? (idx >> 5) : (idx >> 4);
            int nc4  = (TN == 128) ? (idx & 31) : (idx & 15);
            vb[j] = *(const float4*)(Bb + (size_t)(p * 32 + krow) * LDB + bn + nc4 * 4);
        }
    };
    auto storeA = [&](int buf) {
        float* As = AsBase + buf * 32 * PA;
#pragma unroll
        for (int j = 0; j < 4; j++) {
            int idx = tid + j * 256;
            int row = idx >> 3, kc = idx & 7;
            As[(kc * 4 + 0) * PA + row] = t32(va[j].x);
            As[(kc * 4 + 1) * PA + row] = t32(va[j].y);
            As[(kc * 4 + 2) * PA + row] = t32(va[j].z);
            As[(kc * 4 + 3) * PA + row] = t32(va[j].w);
        }
    };
    auto storeB = [&](int buf) {
        float* Bs = BsBase + buf * 32 * PB;
#pragma unroll
        for (int j = 0; j < NB; j++) {
            int idx = tid + j * 256;
            int krow = (TN == 128) ? (idx >> 5) : (idx >> 4);
            int nc4  = (TN == 128) ? (idx & 31) : (idx & 15);
            float4 t;
            t.x = t32(vb[j].x); t.y = t32(vb[j].y);
            t.z = t32(vb[j].z); t.w = t32(vb[j].w);
            *(float4*)(Bs + krow * PB + nc4 * 4) = t;
        }
    };

    float acc[4][NT][4];
#pragma unroll
    for (int mi = 0; mi < 4; mi++)
#pragma unroll
        for (int ni = 0; ni < NT; ni++)
#pragma unroll
            for (int l = 0; l < 4; l++) acc[mi][ni][l] = 0.f;

    int r = lane >> 2, c = lane & 3;

    loadA(0); loadB(0);
    storeA(0); storeB(0);
    __syncthreads();

    for (int p = 0; p < PANELS; p++) {
        int cur = p & 1;
        if (p + 1 < PANELS) { loadA(p + 1); loadB(p + 1); }
        const float* As = AsBase + cur * 32 * PA;
        const float* Bs = BsBase + cur * 32 * PB;
#pragma unroll
        for (int ks = 0; ks < 4; ks++) {
            int k = ks * 8;
            float af[4][4];
#pragma unroll
            for (int mi = 0; mi < 4; mi++) {
                int rb = wm * 64 + mi * 16 + r;
                af[mi][0] = As[(k + c) * PA + rb];
                af[mi][1] = As[(k + c) * PA + rb + 8];
                af[mi][2] = As[(k + c + 4) * PA + rb];
                af[mi][3] = As[(k + c + 4) * PA + rb + 8];
            }
            float bf[NT][2];
#pragma unroll
            for (int ni = 0; ni < NT; ni++) {
                int cb = wn * WNT + ni * 8 + r;
                bf[ni][0] = Bs[(k + c) * PB + cb];
                bf[ni][1] = Bs[(k + c + 4) * PB + cb];
            }
#pragma unroll
            for (int mi = 0; mi < 4; mi++)
#pragma unroll
                for (int ni = 0; ni < NT; ni++)
                    asm volatile(
                        "mma.sync.aligned.m16n8k8.row.col.f32.tf32.tf32.f32 "
                        "{%0,%1,%2,%3},{%4,%5,%6,%7},{%8,%9},{%0,%1,%2,%3};"
                        : "+f"(acc[mi][ni][0]), "+f"(acc[mi][ni][1]),
                          "+f"(acc[mi][ni][2]), "+f"(acc[mi][ni][3])
                        : "r"(fu(af[mi][0])), "r"(fu(af[mi][1])),
                          "r"(fu(af[mi][2])), "r"(fu(af[mi][3])),
                          "r"(fu(bf[ni][0])), "r"(fu(bf[ni][1])));
        }
        if (p + 1 < PANELS) { storeA(cur ^ 1); storeB(cur ^ 1); }
        __syncthreads();
    }

    // epilogue (float2-packed stores)
#pragma unroll
    for (int mi = 0; mi < 4; mi++) {
#pragma unroll
        for (int ni = 0; ni < NT; ni++) {
#pragma unroll
            for (int half = 0; half < 2; half++) {
                int row = bm + wm * 64 + mi * 16 + r + half * 8;
                int colt = bn + wn * WNT + ni * 8 + c * 2;
                float v0 = acc[mi][ni][half * 2 + 0];
                float v1 = acc[mi][ni][half * 2 + 1];
                if constexpr (MODE == 0) {
                    int b = row >> 10, t = row & 1023;
                    int h = colt >> 6, d = colt & 63;
                    float2 o = make_float2(v0 + bias[colt], v1 + bias[colt + 1]);
                    *(float2*)(Out + ((((size_t)b * Hz + h) * Tz + t) * HSz + d)) = o;
                } else if constexpr (MODE == 1) {
                    int t = row & 1023;
                    float gm = gamma[t];
                    float2 o = make_float2((v0 + bias[colt]) * gm,
                                           (v1 + bias[colt + 1]) * gm);
                    *(float2*)(Out + (size_t)row * Cz + colt) = o;
                } else if constexpr (MODE == 2) {
                    float2 o = make_float2(v0 * 0.125f, v1 * 0.125f);
                    *(float2*)(Out + (size_t)z * Tz * Tz + (size_t)row * Tz + colt) = o;
                } else {
                    int b = z >> 4, g = z & 15;
                    float2 o = make_float2(v0, v1);
                    *(float2*)(Out + ((size_t)b * Tz + row) * Cz + g * HSz + colt) = o;
                }
            }
        }
    }
}

// ---------------- RoPE ----------------
__global__ __launch_bounds__(256) void rope_kernel(float* __restrict__ q,
                                                   float* __restrict__ k) {
    int idx = blockIdx.x * 256 + threadIdx.x;   // B*H*T*16 pairs
    int j  = idx & 15;
    int t  = (idx >> 4) & (Tz - 1);
    int bh = idx >> 14;
    double freq = pow(1024.0, -(double)j / 16.0);
    double ang  = (double)t * freq;
    float c = (float)cos(ang);
    float s = (float)sin(ang);
    size_t base = ((size_t)bh * Tz + t) * HSz + j;
    float q0 = q[base], q1 = q[base + 16];
    q[base]      = q0 * c - q1 * s;
    q[base + 16] = q1 * c + q0 * s;
    float k0 = k[base], k1 = k[base + 16];
    k[base]      = k0 * c - k1 * s;
    k[base + 16] = k1 * c + k0 * s;
}

// ---------------- k transpose: [bh][t][d] -> [bh][d][t] ----------------
__global__ __launch_bounds__(256) void ktrans(const float* __restrict__ k,
                                              float* __restrict__ kt) {
    __shared__ float tile[32][33];
    int bh = blockIdx.z;
    int t0 = blockIdx.x * 32;
    int d0 = blockIdx.y * 32;
    int tx = threadIdx.x & 31, ty = threadIdx.x >> 5;
    const float* in = k + (size_t)bh * Tz * HSz;
    float* out = kt + (size_t)bh * Tz * HSz;
#pragma unroll
    for (int i = 0; i < 4; i++)
        tile[ty + i * 8][tx] = in[(size_t)(t0 + ty + i * 8) * HSz + d0 + tx];
    __syncthreads();
#pragma unroll
    for (int i = 0; i < 4; i++)
        out[(size_t)(d0 + ty + i * 8) * Tz + t0 + tx] = tile[tx][ty + i * 8];
}

// ---------------- softmax + w + head-mix (fused) ----------------
__global__ __launch_bounds__(512) void softmax_mix(
    const float* __restrict__ S, float* __restrict__ M2,
    const float* __restrict__ tw, const float* __restrict__ alpha,
    const float* __restrict__ beta, const float* __restrict__ Wmix)
{
    extern __shared__ float sm[];
    const int PR = 1025;
    float* P = sm;                 // [16][1025]
    float* wmix = sm + 16 * PR;    // [256]
    int t = blockIdx.x, b = blockIdx.y;
    int tid = threadIdx.x, lane = tid & 31, h = tid >> 5;   // warp h handles head h

    if (tid < 256) wmix[tid] = Wmix[tid];

    const float4* row = (const float4*)(S + (((size_t)b * Hz + h) * Tz + t) * Tz);
    float4 v[8];
    float mx = -1e30f;
#pragma unroll
    for (int j = 0; j < 8; j++) {
        v[j] = row[lane + j * 32];
        mx = fmaxf(mx, fmaxf(fmaxf(v[j].x, v[j].y), fmaxf(v[j].z, v[j].w)));
    }
#pragma unroll
    for (int o = 16; o; o >>= 1) mx = fmaxf(mx, __shfl_xor_sync(~0u, mx, o));
    float sum = 0.f;
#pragma unroll
    for (int j = 0; j < 8; j++) {
        v[j].x = __expf(v[j].x - mx); v[j].y = __expf(v[j].y - mx);
        v[j].z = __expf(v[j].z - mx); v[j].w = __expf(v[j].w - mx);
        sum += v[j].x + v[j].y + v[j].z + v[j].w;
    }
#pragma unroll
    for (int o = 16; o; o >>= 1) sum += __shfl_xor_sync(~0u, sum, o);
    float bt = beta[h * Tz + t] / sum;
#pragma unroll
    for (int j = 0; j < 8; j++) {
        int s0 = (lane + j * 32) * 4;
        float* vf = (float*)&v[j];
#pragma unroll
        for (int l = 0; l < 4; l++) {
            int s = s0 + l;
            float w = 0.f;
            if (s <= t) w = tw[h * Tz + 1023 + s - t] * alpha[h * Tz + s] * bt;
            P[h * PR + s] = vf[l] * w;
        }
    }
    __syncthreads();
#pragma unroll
    for (int rep = 0; rep < 2; rep++) {
        int s = tid + rep * 512;
        float p[16];
#pragma unroll
        for (int hh = 0; hh < 16; hh++) p[hh] = P[hh * PR + s];
#pragma unroll
        for (int g = 0; g < 16; g++) {
            float a = 0.f;
#pragma unroll
            for (int hh = 0; hh < 16; hh++) a = fmaf(wmix[g * 16 + hh], p[hh], a);
            M2[(((size_t)b * Hz + g) * Tz + t) * Tz + s] = a;
        }
    }
}

// ---------------- launch ----------------
extern "C" void kernel_launch(void* const* d_in, const int* in_sizes, int n_in,
                              void* d_out, int out_size) {
    const float* x          = (const float*)d_in[0];
    const float* time_w     = (const float*)d_in[1];
    const float* time_alpha = (const float*)d_in[2];
    const float* time_beta  = (const float*)d_in[3];
    const float* time_gamma = (const float*)d_in[4];
    const float* Wq = (const float*)d_in[5];
    const float* bq = (const float*)d_in[6];
    const float* Wk = (const float*)d_in[7];
    const float* bk = (const float*)d_in[8];
    const float* Wv = (const float*)d_in[9];
    const float* bv = (const float*)d_in[10];
    const float* Wmix = (const float*)d_in[11];
    const float* Wo = (const float*)d_in[12];
    const float* bo = (const float*)d_in[13];
    float* out = (float*)d_out;

    float *xs, *q, *k, *v, *kt, *y, *S, *M2;
    cudaGetSymbolAddress((void**)&xs, g_xs);
    cudaGetSymbolAddress((void**)&q,  g_q);
    cudaGetSymbolAddress((void**)&k,  g_k);
    cudaGetSymbolAddress((void**)&v,  g_v);
    cudaGetSymbolAddress((void**)&kt, g_kt);
    cudaGetSymbolAddress((void**)&y,  g_y);
    cudaGetSymbolAddress((void**)&S,  g_S);
    cudaGetSymbolAddress((void**)&M2, g_M2);

    constexpr int SM128 = (2 * 32 * 133 + 2 * 32 * 132) * 4;   // 67840
    constexpr int SM64  = (2 * 32 * 133 + 2 * 32 * 68) * 4;    // 51456
    constexpr int SMX   = (16 * 1025 + 256) * 4;               // 66624

    cudaFuncSetAttribute((const void*)gemm_tf32<0, 128, 1024, 1024, 1024>,
                         cudaFuncAttributeMaxDynamicSharedMemorySize, SM128);
    cudaFuncSetAttribute((const void*)gemm_tf32<1, 128, 1024, 1024, 1024>,
                         cudaFuncAttributeMaxDynamicSharedMemorySize, SM128);
    cudaFuncSetAttribute((const void*)gemm_tf32<2, 128, 64, 64, 1024>,
                         cudaFuncAttributeMaxDynamicSharedMemorySize, SM128);
    cudaFuncSetAttribute((const void*)gemm_tf32<3, 64, 1024, 1024, 64>,
                         cudaFuncAttributeMaxDynamicSharedMemorySize, SM64);
    cudaFuncSetAttribute((const void*)softmax_mix,
                         cudaFuncAttributeMaxDynamicSharedMemorySize, SMX);

    shift_kernel<<<(Bz * Tz * Cz) / 256, 256>>>(x, xs);

    // fused QKV
    gemm_tf32<0, 128, 1024, 1024, 1024><<<dim3(24, 16, 1), 256, SM128>>>(
        xs, Wq, Wk, Wv, bq, bk, bv, q, k, v, nullptr);

    rope_kernel<<<(Bz * Hz * Tz * 16) / 256, 256>>>(q, k);

    ktrans<<<dim3(32, 2, Bz * Hz), 256>>>(k, kt);

    // scores
    gemm_tf32<2, 128, 64, 64, 1024><<<dim3(8, 8, Bz * Hz), 256, SM128>>>(
        q, kt, nullptr, nullptr, nullptr, nullptr, nullptr, S, nullptr, nullptr, nullptr);

    softmax_mix<<<dim3(Tz, Bz), 512, SMX>>>(S, M2, time_w, time_alpha, time_beta, Wmix);

    // PV
    gemm_tf32<3, 64, 1024, 1024, 64><<<dim3(1, 8, Bz * Hz), 256, SM64>>>(
        M2, v, nullptr, nullptr, nullptr, nullptr, nullptr, y, nullptr, nullptr, nullptr);

    // output
    gemm_tf32<1, 128, 1024, 1024, 1024><<<dim3(8, 16, 1), 256, SM128>>>(
        y, Wo, nullptr, nullptr, bo, nullptr, nullptr, out, nullptr, nullptr, time_gamma);
}

// round 3
// speedup vs baseline: 2.8718x; 1.2809x over previous
#include <cuda_runtime.h>
#include <cuda_fp16.h>
#include <math.h>

#define Bz 2
#define Tz 1024
#define Cz 1024
#define Hz 16
#define HSz 64

// ---------------- scratch ----------------
__device__ float g_q [Bz * Tz * Cz];
__device__ float g_k [Bz * Tz * Cz];
__device__ float g_v [Bz * Tz * Cz];
__device__ float g_kt[Bz * Tz * Cz];
__device__ float g_y [Bz * Tz * Cz];
__device__ float g_S [(size_t)Bz * Hz * Tz * Tz];
__device__ float g_M2[(size_t)Bz * Hz * Tz * Tz];

__device__ __forceinline__ unsigned packh2(float a, float b) {
    __half2 h = __floats2half2_rn(a, b);
    return *(unsigned*)&h;
}

// ---------------- generic fp16 tensor-core GEMM (fp32 accumulate) ----------------
// MODE 0: fused QKV  (A=x with fused time-shift, logical N=3072, scatter + bias)
// MODE 1: output     (A=y, N=1024, (acc+bias)*gamma[t])
// MODE 2: scores     (batched bh: A=q[bh] 1024x64, B=kt[bh] 64x1024, *0.125)
// MODE 3: PV         (batched bg: A=M2[bg], B=v[bg] 1024x64 -> y[b,t,g*64+d])
template <int MODE, int TN, int KD, int LDA, int LDB>
__global__ __launch_bounds__(256) void gemm_f16(
    const float* __restrict__ A0,
    const float* __restrict__ B0, const float* __restrict__ B1, const float* __restrict__ B2,
    const float* __restrict__ bias0, const float* __restrict__ bias1, const float* __restrict__ bias2,
    float* __restrict__ O0, float* __restrict__ O1, float* __restrict__ O2,
    const float* __restrict__ gamma)
{
    constexpr int PAu = 132;            // uint32 words per Ash k2-row
    constexpr int PBu = TN + 4;         // uint32 words per Bsh k2-row (mult of 4)
    constexpr int NB2 = (TN == 128) ? 2 : 1;
    constexpr int WNT = TN / 4;
    constexpr int NT = WNT / 8;
    constexpr int PANELS = KD / 32;

    __shared__ unsigned Ash[2][16][PAu];
    __shared__ unsigned Bsh[2][16][PBu];

    int tid = threadIdx.x;
    int lane = tid & 31, wid = tid >> 5;
    int wm = wid >> 2, wn = wid & 3;
    int z = blockIdx.z;
    int bm = blockIdx.y * 128;
    int bnL = blockIdx.x * TN;

    const float* Ab = A0;
    const float* Bb = B0;
    const float* bias = bias0;
    float* Out = O0;
    int bn = bnL;
    if constexpr (MODE == 0) {
        int which = bnL >> 10;
        bn = bnL & 1023;
        Bb   = which == 0 ? B0 : (which == 1 ? B1 : B2);
        bias = which == 0 ? bias0 : (which == 1 ? bias1 : bias2);
        Out  = which == 0 ? O0 : (which == 1 ? O1 : O2);
    } else if constexpr (MODE == 2) {
        Ab = A0 + (size_t)z * Tz * HSz;
        Bb = B0 + (size_t)z * Tz * HSz;
    } else if constexpr (MODE == 3) {
        Ab = A0 + (size_t)z * Tz * Tz;
        Bb = B0 + (size_t)z * Tz * HSz;
    }

    float4 va[4], blo[NB2], bhi[NB2];

    auto loadA = [&](int p) {
#pragma unroll
        for (int j = 0; j < 4; j++) {
            int idx = tid + j * 256;
            int row = idx >> 3, kc = idx & 7;
            int kglob = p * 32 + kc * 4;
            if constexpr (MODE == 0) {
                int m = bm + row;
                int b = m >> 10, t = m & 1023;
                const float* src = A0 + ((size_t)b * Tz + t) * Cz + kglob;
                if (kglob < 512) {
                    if (t == 0) va[j] = make_float4(0.f, 0.f, 0.f, 0.f);
                    else        va[j] = *(const float4*)(src - Cz);
                } else {
                    va[j] = *(const float4*)src;
                }
            } else {
                va[j] = *(const float4*)(Ab + (size_t)(bm + row) * LDA + kglob);
            }
        }
    };
    auto loadB = [&](int p) {
#pragma unroll
        for (int j = 0; j < NB2; j++) {
            int idx = tid + j * 256;
            int k2  = (TN == 128) ? (idx >> 5) : (idx >> 4);
            int nc4 = idx & (TN / 4 - 1);
            const float* base = Bb + (size_t)(p * 32 + 2 * k2) * LDB + bn + nc4 * 4;
            blo[j] = *(const float4*)base;
            bhi[j] = *(const float4*)(base + LDB);
        }
    };
    auto storeA = [&](int buf) {
#pragma unroll
        for (int j = 0; j < 4; j++) {
            int idx = tid + j * 256;
            int row = idx >> 3, kc = idx & 7;
            Ash[buf][2 * kc + 0][row] = packh2(va[j].x, va[j].y);
            Ash[buf][2 * kc + 1][row] = packh2(va[j].z, va[j].w);
        }
    };
    auto storeB = [&](int buf) {
#pragma unroll
        for (int j = 0; j < NB2; j++) {
            int idx = tid + j * 256;
            int k2  = (TN == 128) ? (idx >> 5) : (idx >> 4);
            int nc4 = idx & (TN / 4 - 1);
            uint4 t;
            t.x = packh2(blo[j].x, bhi[j].x);
            t.y = packh2(blo[j].y, bhi[j].y);
            t.z = packh2(blo[j].z, bhi[j].z);
            t.w = packh2(blo[j].w, bhi[j].w);
            *(uint4*)&Bsh[buf][k2][nc4 * 4] = t;
        }
    };

    float acc[4][NT][4];
#pragma unroll
    for (int mi = 0; mi < 4; mi++)
#pragma unroll
        for (int ni = 0; ni < NT; ni++)
#pragma unroll
            for (int l = 0; l < 4; l++) acc[mi][ni][l] = 0.f;

    int r = lane >> 2, c = lane & 3;

    loadA(0); loadB(0);
    storeA(0); storeB(0);
    __syncthreads();

    for (int p = 0; p < PANELS; p++) {
        int cur = p & 1;
        if (p + 1 < PANELS) { loadA(p + 1); loadB(p + 1); }
#pragma unroll
        for (int ks = 0; ks < 2; ks++) {
            int kb2 = ks * 8;
            unsigned af[4][4];
#pragma unroll
            for (int mi = 0; mi < 4; mi++) {
                int rb = wm * 64 + mi * 16 + r;
                af[mi][0] = Ash[cur][kb2 + c][rb];
                af[mi][1] = Ash[cur][kb2 + c][rb + 8];
                af[mi][2] = Ash[cur][kb2 + c + 4][rb];
                af[mi][3] = Ash[cur][kb2 + c + 4][rb + 8];
            }
            unsigned bf[NT][2];
#pragma unroll
            for (int ni = 0; ni < NT; ni++) {
                int cb = wn * WNT + ni * 8 + r;
                bf[ni][0] = Bsh[cur][kb2 + c][cb];
                bf[ni][1] = Bsh[cur][kb2 + c + 4][cb];
            }
#pragma unroll
            for (int mi = 0; mi < 4; mi++)
#pragma unroll
                for (int ni = 0; ni < NT; ni++)
                    asm volatile(
                        "mma.sync.aligned.m16n8k16.row.col.f32.f16.f16.f32 "
                        "{%0,%1,%2,%3},{%4,%5,%6,%7},{%8,%9},{%0,%1,%2,%3};"
                        : "+f"(acc[mi][ni][0]), "+f"(acc[mi][ni][1]),
                          "+f"(acc[mi][ni][2]), "+f"(acc[mi][ni][3])
                        : "r"(af[mi][0]), "r"(af[mi][1]),
                          "r"(af[mi][2]), "r"(af[mi][3]),
                          "r"(bf[ni][0]), "r"(bf[ni][1]));
        }
        if (p + 1 < PANELS) { storeA(cur ^ 1); storeB(cur ^ 1); }
        __syncthreads();
    }

    // epilogue (float2-packed stores)
#pragma unroll
    for (int mi = 0; mi < 4; mi++) {
#pragma unroll
        for (int ni = 0; ni < NT; ni++) {
#pragma unroll
            for (int half = 0; half < 2; half++) {
                int row = bm + wm * 64 + mi * 16 + r + half * 8;
                int colt = bn + wn * WNT + ni * 8 + c * 2;
                float v0 = acc[mi][ni][half * 2 + 0];
                float v1 = acc[mi][ni][half * 2 + 1];
                if constexpr (MODE == 0) {
                    int b = row >> 10, t = row & 1023;
                    int h = colt >> 6, d = colt & 63;
                    float2 o = make_float2(v0 + bias[colt], v1 + bias[colt + 1]);
                    *(float2*)(Out + ((((size_t)b * Hz + h) * Tz + t) * HSz + d)) = o;
                } else if constexpr (MODE == 1) {
                    int t = row & 1023;
                    float gm = gamma[t];
                    float2 o = make_float2((v0 + bias[colt]) * gm,
                                           (v1 + bias[colt + 1]) * gm);
                    *(float2*)(Out + (size_t)row * Cz + colt) = o;
                } else if constexpr (MODE == 2) {
                    float2 o = make_float2(v0 * 0.125f, v1 * 0.125f);
                    *(float2*)(Out + (size_t)z * Tz * Tz + (size_t)row * Tz + colt) = o;
                } else {
                    int b = z >> 4, g = z & 15;
                    float2 o = make_float2(v0, v1);
                    *(float2*)(Out + ((size_t)b * Tz + row) * Cz + g * HSz + colt) = o;
                }
            }
        }
    }
}

// ---------------- RoPE ----------------
__global__ __launch_bounds__(256) void rope_kernel(float* __restrict__ q,
                                                   float* __restrict__ k) {
    int idx = blockIdx.x * 256 + threadIdx.x;   // B*H*T*16 pairs
    int j  = idx & 15;
    int t  = (idx >> 4) & (Tz - 1);
    int bh = idx >> 14;
    double freq = pow(1024.0, -(double)j / 16.0);
    double ang  = (double)t * freq;
    float c = (float)cos(ang);
    float s = (float)sin(ang);
    size_t base = ((size_t)bh * Tz + t) * HSz + j;
    float q0 = q[base], q1 = q[base + 16];
    q[base]      = q0 * c - q1 * s;
    q[base + 16] = q1 * c + q0 * s;
    float k0 = k[base], k1 = k[base + 16];
    k[base]      = k0 * c - k1 * s;
    k[base + 16] = k1 * c + k0 * s;
}

// ---------------- k transpose: [bh][t][d] -> [bh][d][t] ----------------
__global__ __launch_bounds__(256) void ktrans(const float* __restrict__ k,
                                              float* __restrict__ kt) {
    __shared__ float tile[32][33];
    int bh = blockIdx.z;
    int t0 = blockIdx.x * 32;
    int d0 = blockIdx.y * 32;
    int tx = threadIdx.x & 31, ty = threadIdx.x >> 5;
    const float* in = k + (size_t)bh * Tz * HSz;
    float* out = kt + (size_t)bh * Tz * HSz;
#pragma unroll
    for (int i = 0; i < 4; i++)
        tile[ty + i * 8][tx] = in[(size_t)(t0 + ty + i * 8) * HSz + d0 + tx];
    __syncthreads();
#pragma unroll
    for (int i = 0; i < 4; i++)
        out[(size_t)(d0 + ty + i * 8) * Tz + t0 + tx] = tile[tx][ty + i * 8];
}

// ---------------- softmax + w + head-mix (fused) ----------------
__global__ __launch_bounds__(512) void softmax_mix(
    const float* __restrict__ S, float* __restrict__ M2,
    const float* __restrict__ tw, const float* __restrict__ alpha,
    const float* __restrict__ beta, const float* __restrict__ Wmix)
{
    extern __shared__ float sm[];
    const int PR = 1025;
    float* P = sm;                 // [16][1025]
    float* wmix = sm + 16 * PR;    // [256]
    int t = blockIdx.x, b = blockIdx.y;
    int tid = threadIdx.x, lane = tid & 31, h = tid >> 5;

    if (tid < 256) wmix[tid] = Wmix[tid];

    const float4* row = (const float4*)(S + (((size_t)b * Hz + h) * Tz + t) * Tz);
    float4 v[8];
    float mx = -1e30f;
#pragma unroll
    for (int j = 0; j < 8; j++) {
        v[j] = row[lane + j * 32];
        mx = fmaxf(mx, fmaxf(fmaxf(v[j].x, v[j].y), fmaxf(v[j].z, v[j].w)));
    }
#pragma unroll
    for (int o = 16; o; o >>= 1) mx = fmaxf(mx, __shfl_xor_sync(~0u, mx, o));
    float sum = 0.f;
#pragma unroll
    for (int j = 0; j < 8; j++) {
        v[j].x = __expf(v[j].x - mx); v[j].y = __expf(v[j].y - mx);
        v[j].z = __expf(v[j].z - mx); v[j].w = __expf(v[j].w - mx);
        sum += v[j].x + v[j].y + v[j].z + v[j].w;
    }
#pragma unroll
    for (int o = 16; o; o >>= 1) sum += __shfl_xor_sync(~0u, sum, o);
    float bt = beta[h * Tz + t] / sum;
#pragma unroll
    for (int j = 0; j < 8; j++) {
        int s0 = (lane + j * 32) * 4;
        float* vf = (float*)&v[j];
#pragma unroll
        for (int l = 0; l < 4; l++) {
            int s = s0 + l;
            float w = 0.f;
            if (s <= t) w = tw[h * Tz + 1023 + s - t] * alpha[h * Tz + s] * bt;
            P[h * PR + s] = vf[l] * w;
        }
    }
    __syncthreads();
#pragma unroll
    for (int rep = 0; rep < 2; rep++) {
        int s = tid + rep * 512;
        float p[16];
#pragma unroll
        for (int hh = 0; hh < 16; hh++) p[hh] = P[hh * PR + s];
#pragma unroll
        for (int g = 0; g < 16; g++) {
            float a = 0.f;
#pragma unroll
            for (int hh = 0; hh < 16; hh++) a = fmaf(wmix[g * 16 + hh], p[hh], a);
            M2[(((size_t)b * Hz + g) * Tz + t) * Tz + s] = a;
        }
    }
}

// ---------------- launch ----------------
extern "C" void kernel_launch(void* const* d_in, const int* in_sizes, int n_in,
                              void* d_out, int out_size) {
    const float* x          = (const float*)d_in[0];
    const float* time_w     = (const float*)d_in[1];
    const float* time_alpha = (const float*)d_in[2];
    const float* time_beta  = (const float*)d_in[3];
    const float* time_gamma = (const float*)d_in[4];
    const float* Wq = (const float*)d_in[5];
    const float* bq = (const float*)d_in[6];
    const float* Wk = (const float*)d_in[7];
    const float* bk = (const float*)d_in[8];
    const float* Wv = (const float*)d_in[9];
    const float* bv = (const float*)d_in[10];
    const float* Wmix = (const float*)d_in[11];
    const float* Wo = (const float*)d_in[12];
    const float* bo = (const float*)d_in[13];
    float* out = (float*)d_out;

    float *q, *k, *v, *kt, *y, *S, *M2;
    cudaGetSymbolAddress((void**)&q,  g_q);
    cudaGetSymbolAddress((void**)&k,  g_k);
    cudaGetSymbolAddress((void**)&v,  g_v);
    cudaGetSymbolAddress((void**)&kt, g_kt);
    cudaGetSymbolAddress((void**)&y,  g_y);
    cudaGetSymbolAddress((void**)&S,  g_S);
    cudaGetSymbolAddress((void**)&M2, g_M2);

    constexpr int SMX = (16 * 1025 + 256) * 4;   // 66624
    cudaFuncSetAttribute((const void*)softmax_mix,
                         cudaFuncAttributeMaxDynamicSharedMemorySize, SMX);

    // fused time-shift + QKV
    gemm_f16<0, 128, 1024, 1024, 1024><<<dim3(24, 16, 1), 256>>>(
        x, Wq, Wk, Wv, bq, bk, bv, q, k, v, nullptr);

    rope_kernel<<<(Bz * Hz * Tz * 16) / 256, 256>>>(q, k);

    ktrans<<<dim3(32, 2, Bz * Hz), 256>>>(k, kt);

    // scores
    gemm_f16<2, 128, 64, 64, 1024><<<dim3(8, 8, Bz * Hz), 256>>>(
        q, kt, nullptr, nullptr, nullptr, nullptr, nullptr, S, nullptr, nullptr, nullptr);

    softmax_mix<<<dim3(Tz, Bz), 512, SMX>>>(S, M2, time_w, time_alpha, time_beta, Wmix);

    // PV
    gemm_f16<3, 64, 1024, 1024, 64><<<dim3(1, 8, Bz * Hz), 256>>>(
        M2, v, nullptr, nullptr, nullptr, nullptr, nullptr, y, nullptr, nullptr, nullptr);

    // output
    gemm_f16<1, 128, 1024, 1024, 1024><<<dim3(8, 16, 1), 256>>>(
        y, Wo, nullptr, nullptr, bo, nullptr, nullptr, out, nullptr, nullptr, time_gamma);
}

// round 4
// speedup vs baseline: 4.3240x; 1.5057x over previous
#include <cuda_runtime.h>
#include <cuda_fp16.h>
#include <math.h>

#define Bz 2
#define Tz 1024
#define Cz 1024
#define Hz 16
#define HSz 64

// ---------------- scratch ----------------
__device__ __half  g_xsh[Bz * Tz * Cz];                 // shifted x, half
__device__ unsigned g_Wqp[Cz / 2 * Cz];                  // packed (k,k+1) weights
__device__ unsigned g_Wkp[Cz / 2 * Cz];
__device__ unsigned g_Wvp[Cz / 2 * Cz];
__device__ unsigned g_Wop[Cz / 2 * Cz];
__device__ float   g_q [Bz * Tz * Cz];                   // fp32 q (pre-rope)
__device__ float   g_k [Bz * Tz * Cz];
__device__ float   g_v [Bz * Tz * Cz];
__device__ __half  g_qh[Bz * Tz * Cz];                   // post-rope half
__device__ __half  g_kh[Bz * Tz * Cz];
__device__ unsigned g_ktp[Bz * Hz * (HSz / 2) * Tz];     // packed k^T [bh][d2][t]
__device__ unsigned g_vp [Bz * Hz * (Tz / 2) * HSz];     // packed v [bh][s2][d]
__device__ float   g_S [(size_t)Bz * Hz * Tz * Tz];      // scores fp32
__device__ __half  g_M2[(size_t)Bz * Hz * Tz * Tz];      // mixed attention, half
__device__ __half  g_yh[Bz * Tz * Cz];                   // PV result, half

__device__ __forceinline__ unsigned packh2(float a, float b) {
    __half2 h = __floats2half2_rn(a, b);
    return *(unsigned*)&h;
}

// ---------------- prep: shift + cvt x -> xsh (half) ----------------
__global__ __launch_bounds__(256) void shift_cvt(const float* __restrict__ x,
                                                 __half* __restrict__ xsh) {
    int w = blockIdx.x * 256 + threadIdx.x;      // 1M words (2 halves each)
    int c2 = w & 511;
    int t = (w >> 9) & 1023;
    int b = w >> 19;
    int c = c2 * 2;
    float2 val;
    if (c < 512) {
        if (t == 0) val = make_float2(0.f, 0.f);
        else        val = *(const float2*)(x + ((size_t)b * Tz + t - 1) * Cz + c);
    } else {
        val = *(const float2*)(x + ((size_t)b * Tz + t) * Cz + c);
    }
    ((unsigned*)xsh)[w] = packh2(val.x, val.y);
}

// ---------------- prep: pack W [1024][1024] fp32 -> [512][1024] half2 words ----
__global__ __launch_bounds__(512) void wpack(const float* __restrict__ W,
                                             unsigned* __restrict__ Wp) {
    int w = blockIdx.x * 512 + threadIdx.x;      // 512K words
    int n = w & 1023;
    int k2 = w >> 10;
    float a = W[(size_t)(2 * k2) * Cz + n];
    float b = W[(size_t)(2 * k2 + 1) * Cz + n];
    Wp[w] = packh2(a, b);
}

// ---------------- prep: pack v [bh][s][64] -> [bh][s2][64] (s,s+1) words ------
__global__ __launch_bounds__(256) void vpack(const float* __restrict__ v,
                                             unsigned* __restrict__ vp) {
    int w = blockIdx.x * 256 + threadIdx.x;      // 1M words
    int d = w & 63;
    int s2 = (w >> 6) & 511;
    int bh = w >> 15;
    const float* base = v + ((size_t)bh * Tz + 2 * s2) * HSz + d;
    vp[w] = packh2(base[0], base[HSz]);
}

// ---------------- rope + cvt to half ----------------
__global__ __launch_bounds__(256) void rope_cvt(const float* __restrict__ q,
                                                const float* __restrict__ k,
                                                __half* __restrict__ qh,
                                                __half* __restrict__ kh) {
    int idx = blockIdx.x * 256 + threadIdx.x;   // B*H*T*16
    int j  = idx & 15;
    int t  = (idx >> 4) & (Tz - 1);
    int bh = idx >> 14;
    float freq = exp2f(-0.625f * (float)j);
    float ang  = (float)t * freq;
    float c, s;
    sincosf(ang, &s, &c);
    size_t base = ((size_t)bh * Tz + t) * HSz + j;
    float q0 = q[base], q1 = q[base + 16];
    qh[base]      = __float2half(q0 * c - q1 * s);
    qh[base + 16] = __float2half(q1 * c + q0 * s);
    qh[base + 32] = __float2half(q[base + 32]);
    qh[base + 48] = __float2half(q[base + 48]);
    float k0 = k[base], k1 = k[base + 16];
    kh[base]      = __float2half(k0 * c - k1 * s);
    kh[base + 16] = __float2half(k1 * c + k0 * s);
    kh[base + 32] = __float2half(k[base + 32]);
    kh[base + 48] = __float2half(k[base + 48]);
}

// ---------------- kh (uint32 view [t][32]) -> ktp [d2][t] transpose ------------
__global__ __launch_bounds__(256) void ktrans32(const __half* __restrict__ kh,
                                                unsigned* __restrict__ ktp) {
    __shared__ unsigned tile[32][33];
    int bh = blockIdx.y;
    int t0 = blockIdx.x * 32;
    int tx = threadIdx.x & 31, ty = threadIdx.x >> 5;
    const unsigned* in = (const unsigned*)kh + (size_t)bh * Tz * 32;
    unsigned* out = ktp + (size_t)bh * 32 * Tz;
#pragma unroll
    for (int i = 0; i < 4; i++)
        tile[ty + i * 8][tx] = in[(size_t)(t0 + ty + i * 8) * 32 + tx];
    __syncthreads();
#pragma unroll
    for (int i = 0; i < 4; i++)
        out[(size_t)(ty + i * 8) * Tz + t0 + tx] = tile[tx][ty + i * 8];
}

// ---------------- generic fp16-native tensor-core GEMM ----------------
// A: half [row][k] (pairs natural), B: packed uint32 [k2][n]
// MODE 0: QKV  (N logical 3072, scatter fp32 q/k/v + bias)
// MODE 1: output (fp32 out, (acc+bias)*gamma)
// MODE 2: scores (S fp32, *0.125), batched bh
// MODE 3: PV (yh half out), batched bg
template <int MODE, int TN, int KD, int LDA, int LDBW>
__global__ __launch_bounds__(256) void gemm_h(
    const __half* __restrict__ A0,
    const unsigned* __restrict__ B0, const unsigned* __restrict__ B1, const unsigned* __restrict__ B2,
    const float* __restrict__ bias0, const float* __restrict__ bias1, const float* __restrict__ bias2,
    float* __restrict__ O0, float* __restrict__ O1, float* __restrict__ O2,
    const float* __restrict__ gamma)
{
    constexpr int PAu = 132;
    constexpr int PBu = TN + 4;
    constexpr int NBB = (TN == 128) ? 2 : 1;
    constexpr int WNT = TN / 4;
    constexpr int NT = WNT / 8;
    constexpr int PANELS = KD / 32;

    __shared__ unsigned Ash[2][16][PAu];
    __shared__ unsigned Bsh[2][16][PBu];

    int tid = threadIdx.x;
    int lane = tid & 31, wid = tid >> 5;
    int wm = wid >> 2, wn = wid & 3;
    int z = blockIdx.z;
    int bm = blockIdx.y * 128;
    int bnL = blockIdx.x * TN;

    const __half* Ab = A0;
    const unsigned* Bb = B0;
    const float* bias = bias0;
    float* Out = O0;
    int bn = bnL;
    if constexpr (MODE == 0) {
        int which = bnL >> 10;
        bn = bnL & 1023;
        Bb   = which == 0 ? B0 : (which == 1 ? B1 : B2);
        bias = which == 0 ? bias0 : (which == 1 ? bias1 : bias2);
        Out  = which == 0 ? O0 : (which == 1 ? O1 : O2);
    } else if constexpr (MODE == 2) {
        Ab = A0 + (size_t)z * Tz * HSz;
        Bb = B0 + (size_t)z * (HSz / 2) * Tz;
    } else if constexpr (MODE == 3) {
        Ab = A0 + (size_t)z * Tz * Tz;
        Bb = B0 + (size_t)z * (Tz / 2) * HSz;
    }

    uint4 va[2], vbv[NBB];

    auto loadA = [&](int p) {
#pragma unroll
        for (int j = 0; j < 2; j++) {
            int idx = tid + j * 256;
            int row = idx >> 2, kc8 = idx & 3;
            va[j] = *(const uint4*)(Ab + (size_t)(bm + row) * LDA + p * 32 + kc8 * 8);
        }
    };
    auto loadB = [&](int p) {
#pragma unroll
        for (int j = 0; j < NBB; j++) {
            int idx = tid + j * 256;
            int k2r = (TN == 128) ? (idx >> 5) : (idx >> 4);
            int nc4 = idx & (TN / 4 - 1);
            vbv[j] = *(const uint4*)(Bb + (size_t)(p * 16 + k2r) * LDBW + bn + nc4 * 4);
        }
    };
    auto storeA = [&](int buf) {
#pragma unroll
        for (int j = 0; j < 2; j++) {
            int idx = tid + j * 256;
            int row = idx >> 2, kc8 = idx & 3;
            Ash[buf][kc8 * 4 + 0][row] = va[j].x;
            Ash[buf][kc8 * 4 + 1][row] = va[j].y;
            Ash[buf][kc8 * 4 + 2][row] = va[j].z;
            Ash[buf][kc8 * 4 + 3][row] = va[j].w;
        }
    };
    auto storeB = [&](int buf) {
#pragma unroll
        for (int j = 0; j < NBB; j++) {
            int idx = tid + j * 256;
            int k2r = (TN == 128) ? (idx >> 5) : (idx >> 4);
            int nc4 = idx & (TN / 4 - 1);
            *(uint4*)&Bsh[buf][k2r][nc4 * 4] = vbv[j];
        }
    };

    float acc[4][NT][4];
#pragma unroll
    for (int mi = 0; mi < 4; mi++)
#pragma unroll
        for (int ni = 0; ni < NT; ni++)
#pragma unroll
            for (int l = 0; l < 4; l++) acc[mi][ni][l] = 0.f;

    int r = lane >> 2, c = lane & 3;

    loadA(0); loadB(0);
    storeA(0); storeB(0);
    __syncthreads();

    for (int p = 0; p < PANELS; p++) {
        int cur = p & 1;
        if (p + 1 < PANELS) { loadA(p + 1); loadB(p + 1); }
#pragma unroll
        for (int ks = 0; ks < 2; ks++) {
            int kb2 = ks * 8;
            unsigned af[4][4];
#pragma unroll
            for (int mi = 0; mi < 4; mi++) {
                int rb = wm * 64 + mi * 16 + r;
                af[mi][0] = Ash[cur][kb2 + c][rb];
                af[mi][1] = Ash[cur][kb2 + c][rb + 8];
                af[mi][2] = Ash[cur][kb2 + c + 4][rb];
                af[mi][3] = Ash[cur][kb2 + c + 4][rb + 8];
            }
            unsigned bf[NT][2];
#pragma unroll
            for (int ni = 0; ni < NT; ni++) {
                int cb = wn * WNT + ni * 8 + r;
                bf[ni][0] = Bsh[cur][kb2 + c][cb];
                bf[ni][1] = Bsh[cur][kb2 + c + 4][cb];
            }
#pragma unroll
            for (int mi = 0; mi < 4; mi++)
#pragma unroll
                for (int ni = 0; ni < NT; ni++)
                    asm volatile(
                        "mma.sync.aligned.m16n8k16.row.col.f32.f16.f16.f32 "
                        "{%0,%1,%2,%3},{%4,%5,%6,%7},{%8,%9},{%0,%1,%2,%3};"
                        : "+f"(acc[mi][ni][0]), "+f"(acc[mi][ni][1]),
                          "+f"(acc[mi][ni][2]), "+f"(acc[mi][ni][3])
                        : "r"(af[mi][0]), "r"(af[mi][1]),
                          "r"(af[mi][2]), "r"(af[mi][3]),
                          "r"(bf[ni][0]), "r"(bf[ni][1]));
        }
        if (p + 1 < PANELS) { storeA(cur ^ 1); storeB(cur ^ 1); }
        __syncthreads();
    }

#pragma unroll
    for (int mi = 0; mi < 4; mi++) {
#pragma unroll
        for (int ni = 0; ni < NT; ni++) {
#pragma unroll
            for (int half = 0; half < 2; half++) {
                int row = bm + wm * 64 + mi * 16 + r + half * 8;
                int colt = bn + wn * WNT + ni * 8 + c * 2;
                float v0 = acc[mi][ni][half * 2 + 0];
                float v1 = acc[mi][ni][half * 2 + 1];
                if constexpr (MODE == 0) {
                    int b = row >> 10, t = row & 1023;
                    int h = colt >> 6, d = colt & 63;
                    float2 o = make_float2(v0 + bias[colt], v1 + bias[colt + 1]);
                    *(float2*)(Out + ((((size_t)b * Hz + h) * Tz + t) * HSz + d)) = o;
                } else if constexpr (MODE == 1) {
                    int t = row & 1023;
                    float gm = gamma[t];
                    float2 o = make_float2((v0 + bias[colt]) * gm,
                                           (v1 + bias[colt + 1]) * gm);
                    *(float2*)(Out + (size_t)row * Cz + colt) = o;
                } else if constexpr (MODE == 2) {
                    float2 o = make_float2(v0 * 0.125f, v1 * 0.125f);
                    *(float2*)(Out + (size_t)z * Tz * Tz + (size_t)row * Tz + colt) = o;
                } else {
                    int b = z >> 4, g = z & 15;
                    unsigned* yw = (unsigned*)Out;
                    size_t hidx = ((size_t)b * Tz + row) * Cz + g * HSz + colt;
                    yw[hidx >> 1] = packh2(v0, v1);
                }
            }
        }
    }
}

// ---------------- softmax + w + head-mix (fused), M2 out as half ---------------
__global__ __launch_bounds__(512) void softmax_mix(
    const float* __restrict__ S, unsigned* __restrict__ M2w,
    const float* __restrict__ tw, const float* __restrict__ alpha,
    const float* __restrict__ beta, const float* __restrict__ Wmix)
{
    extern __shared__ float sm[];
    const int PR = 1026;
    float* P = sm;                 // [16][1026]
    float* wmix = sm + 16 * PR;    // [256]
    int t = blockIdx.x, b = blockIdx.y;
    int tid = threadIdx.x, lane = tid & 31, h = tid >> 5;

    if (tid < 256) wmix[tid] = Wmix[tid];

    const float4* row = (const float4*)(S + (((size_t)b * Hz + h) * Tz + t) * Tz);
    float4 v[8];
    float mx = -1e30f;
#pragma unroll
    for (int j = 0; j < 8; j++) {
        v[j] = row[lane + j * 32];
        mx = fmaxf(mx, fmaxf(fmaxf(v[j].x, v[j].y), fmaxf(v[j].z, v[j].w)));
    }
#pragma unroll
    for (int o = 16; o; o >>= 1) mx = fmaxf(mx, __shfl_xor_sync(~0u, mx, o));
    float sum = 0.f;
#pragma unroll
    for (int j = 0; j < 8; j++) {
        v[j].x = __expf(v[j].x - mx); v[j].y = __expf(v[j].y - mx);
        v[j].z = __expf(v[j].z - mx); v[j].w = __expf(v[j].w - mx);
        sum += v[j].x + v[j].y + v[j].z + v[j].w;
    }
#pragma unroll
    for (int o = 16; o; o >>= 1) sum += __shfl_xor_sync(~0u, sum, o);
    float bt = beta[h * Tz + t] / sum;
#pragma unroll
    for (int j = 0; j < 8; j++) {
        int s0 = (lane + j * 32) * 4;
        float* vf = (float*)&v[j];
#pragma unroll
        for (int l = 0; l < 4; l++) {
            int s = s0 + l;
            float w = 0.f;
            if (s <= t) w = tw[h * Tz + 1023 + s - t] * alpha[h * Tz + s] * bt;
            P[h * PR + s] = vf[l] * w;
        }
    }
    __syncthreads();
    {
        int s2 = tid;   // pair (2*tid, 2*tid+1)
        float2 p2[16];
#pragma unroll
        for (int hh = 0; hh < 16; hh++)
            p2[hh] = *(float2*)&P[hh * PR + 2 * s2];
#pragma unroll
        for (int g = 0; g < 16; g++) {
            float a0 = 0.f, a1 = 0.f;
#pragma unroll
            for (int hh = 0; hh < 16; hh++) {
                float wv = wmix[g * 16 + hh];
                a0 = fmaf(wv, p2[hh].x, a0);
                a1 = fmaf(wv, p2[hh].y, a1);
            }
            M2w[(((size_t)b * Hz + g) * Tz + t) * (Tz / 2) + s2] = packh2(a0, a1);
        }
    }
}

// ---------------- launch ----------------
extern "C" void kernel_launch(void* const* d_in, const int* in_sizes, int n_in,
                              void* d_out, int out_size) {
    const float* x          = (const float*)d_in[0];
    const float* time_w     = (const float*)d_in[1];
    const float* time_alpha = (const float*)d_in[2];
    const float* time_beta  = (const float*)d_in[3];
    const float* time_gamma = (const float*)d_in[4];
    const float* Wq = (const float*)d_in[5];
    const float* bq = (const float*)d_in[6];
    const float* Wk = (const float*)d_in[7];
    const float* bk = (const float*)d_in[8];
    const float* Wv = (const float*)d_in[9];
    const float* bv = (const float*)d_in[10];
    const float* Wmix = (const float*)d_in[11];
    const float* Wo = (const float*)d_in[12];
    const float* bo = (const float*)d_in[13];
    float* out = (float*)d_out;

    __half *xsh, *qh, *kh, *yh, *M2;
    unsigned *Wqp, *Wkp, *Wvp, *Wop, *ktp, *vp;
    float *q, *k, *v, *S;
    cudaGetSymbolAddress((void**)&xsh, g_xsh);
    cudaGetSymbolAddress((void**)&Wqp, g_Wqp);
    cudaGetSymbolAddress((void**)&Wkp, g_Wkp);
    cudaGetSymbolAddress((void**)&Wvp, g_Wvp);
    cudaGetSymbolAddress((void**)&Wop, g_Wop);
    cudaGetSymbolAddress((void**)&q,  g_q);
    cudaGetSymbolAddress((void**)&k,  g_k);
    cudaGetSymbolAddress((void**)&v,  g_v);
    cudaGetSymbolAddress((void**)&qh, g_qh);
    cudaGetSymbolAddress((void**)&kh, g_kh);
    cudaGetSymbolAddress((void**)&ktp, g_ktp);
    cudaGetSymbolAddress((void**)&vp, g_vp);
    cudaGetSymbolAddress((void**)&S,  g_S);
    cudaGetSymbolAddress((void**)&M2, g_M2);
    cudaGetSymbolAddress((void**)&yh, g_yh);

    constexpr int SMX = (16 * 1026 + 256) * 4;
    cudaFuncSetAttribute((const void*)softmax_mix,
                         cudaFuncAttributeMaxDynamicSharedMemorySize, SMX);

    // prep
    shift_cvt<<<(Bz * Tz * Cz / 2) / 256, 256>>>(x, xsh);
    wpack<<<1024, 512>>>(Wq, Wqp);
    wpack<<<1024, 512>>>(Wk, Wkp);
    wpack<<<1024, 512>>>(Wv, Wvp);
    wpack<<<1024, 512>>>(Wo, Wop);

    // QKV
    gemm_h<0, 128, 1024, 1024, 1024><<<dim3(24, 16, 1), 256>>>(
        xsh, Wqp, Wkp, Wvp, bq, bk, bv, q, k, v, nullptr);

    rope_cvt<<<(Bz * Hz * Tz * 16) / 256, 256>>>(q, k, qh, kh);
    ktrans32<<<dim3(32, Bz * Hz), 256>>>(kh, ktp);
    vpack<<<(Bz * Hz * (Tz / 2) * HSz) / 256, 256>>>(v, vp);

    // scores
    gemm_h<2, 128, 64, 64, 1024><<<dim3(8, 8, Bz * Hz), 256>>>(
        qh, ktp, nullptr, nullptr, nullptr, nullptr, nullptr, S, nullptr, nullptr, nullptr);

    softmax_mix<<<dim3(Tz, Bz), 512, SMX>>>(S, (unsigned*)M2, time_w, time_alpha,
                                            time_beta, Wmix);

    // PV  (yh half out)
    gemm_h<3, 64, 1024, 1024, 64><<<dim3(1, 8, Bz * Hz), 256>>>(
        M2, vp, nullptr, nullptr, nullptr, nullptr, nullptr, (float*)yh, nullptr, nullptr, nullptr);

    // output
    gemm_h<1, 128, 1024, 1024, 1024><<<dim3(8, 16, 1), 256>>>(
        yh, Wop, nullptr, nullptr, bo, nullptr, nullptr, out, nullptr, nullptr, time_gamma);
}

// round 5
// speedup vs baseline: 5.2023x; 1.2031x over previous
#include <cuda_runtime.h>
#include <cuda_fp16.h>
#include <math.h>

#define Bz 2
#define Tz 1024
#define Cz 1024
#define Hz 16
#define HSz 64

// ---------------- scratch ----------------
__device__ __half  g_xsh[Bz * Tz * Cz];
__device__ unsigned g_Wqp[Cz / 2 * Cz];
__device__ unsigned g_Wkp[Cz / 2 * Cz];
__device__ unsigned g_Wvp[Cz / 2 * Cz];
__device__ unsigned g_Wop[Cz / 2 * Cz];
__device__ float   g_q [Bz * Tz * Cz];
__device__ float   g_k [Bz * Tz * Cz];
__device__ float   g_v [Bz * Tz * Cz];
__device__ __half  g_qh[Bz * Tz * Cz];
__device__ __half  g_kh[Bz * Tz * Cz];
__device__ unsigned g_ktp[Bz * Hz * (HSz / 2) * Tz];
__device__ unsigned g_vp [Bz * Hz * (Tz / 2) * HSz];
__device__ float   g_S [(size_t)Bz * Hz * Tz * Tz];
__device__ __half  g_M2[(size_t)Bz * Hz * Tz * Tz];
__device__ __half  g_yh[Bz * Tz * Cz];

__device__ __forceinline__ unsigned packh2(float a, float b) {
    __half2 h = __floats2half2_rn(a, b);
    return *(unsigned*)&h;
}
__device__ __forceinline__ void cpa16(unsigned dst, const void* src) {
    asm volatile("cp.async.cg.shared.global [%0], [%1], 16;" :: "r"(dst), "l"(src));
}
__device__ __forceinline__ void cpcommit() {
    asm volatile("cp.async.commit_group;");
}

// ---------------- prep kernels ----------------
__global__ __launch_bounds__(256) void shift_cvt(const float* __restrict__ x,
                                                 __half* __restrict__ xsh) {
    int w = blockIdx.x * 256 + threadIdx.x;
    int c2 = w & 511;
    int t = (w >> 9) & 1023;
    int b = w >> 19;
    int c = c2 * 2;
    float2 val;
    if (c < 512) {
        if (t == 0) val = make_float2(0.f, 0.f);
        else        val = *(const float2*)(x + ((size_t)b * Tz + t - 1) * Cz + c);
    } else {
        val = *(const float2*)(x + ((size_t)b * Tz + t) * Cz + c);
    }
    ((unsigned*)xsh)[w] = packh2(val.x, val.y);
}

__global__ __launch_bounds__(512) void wpack(const float* __restrict__ W,
                                             unsigned* __restrict__ Wp) {
    int w = blockIdx.x * 512 + threadIdx.x;
    int n = w & 1023;
    int k2 = w >> 10;
    float a = W[(size_t)(2 * k2) * Cz + n];
    float b = W[(size_t)(2 * k2 + 1) * Cz + n];
    Wp[w] = packh2(a, b);
}

__global__ __launch_bounds__(256) void vpack(const float* __restrict__ v,
                                             unsigned* __restrict__ vp) {
    int w = blockIdx.x * 256 + threadIdx.x;
    int d = w & 63;
    int s2 = (w >> 6) & 511;
    int bh = w >> 15;
    const float* base = v + ((size_t)bh * Tz + 2 * s2) * HSz + d;
    vp[w] = packh2(base[0], base[HSz]);
}

__global__ __launch_bounds__(256) void rope_cvt(const float* __restrict__ q,
                                                const float* __restrict__ k,
                                                __half* __restrict__ qh,
                                                __half* __restrict__ kh) {
    int idx = blockIdx.x * 256 + threadIdx.x;
    int j  = idx & 15;
    int t  = (idx >> 4) & (Tz - 1);
    int bh = idx >> 14;
    float freq = exp2f(-0.625f * (float)j);
    float ang  = (float)t * freq;
    float c, s;
    sincosf(ang, &s, &c);
    size_t base = ((size_t)bh * Tz + t) * HSz + j;
    float q0 = q[base], q1 = q[base + 16];
    qh[base]      = __float2half(q0 * c - q1 * s);
    qh[base + 16] = __float2half(q1 * c + q0 * s);
    qh[base + 32] = __float2half(q[base + 32]);
    qh[base + 48] = __float2half(q[base + 48]);
    float k0 = k[base], k1 = k[base + 16];
    kh[base]      = __float2half(k0 * c - k1 * s);
    kh[base + 16] = __float2half(k1 * c + k0 * s);
    kh[base + 32] = __float2half(k[base + 32]);
    kh[base + 48] = __float2half(k[base + 48]);
}

__global__ __launch_bounds__(256) void ktrans32(const __half* __restrict__ kh,
                                                unsigned* __restrict__ ktp) {
    __shared__ unsigned tile[32][33];
    int bh = blockIdx.y;
    int t0 = blockIdx.x * 32;
    int tx = threadIdx.x & 31, ty = threadIdx.x >> 5;
    const unsigned* in = (const unsigned*)kh + (size_t)bh * Tz * 32;
    unsigned* out = ktp + (size_t)bh * 32 * Tz;
#pragma unroll
    for (int i = 0; i < 4; i++)
        tile[ty + i * 8][tx] = in[(size_t)(t0 + ty + i * 8) * 32 + tx];
    __syncthreads();
#pragma unroll
    for (int i = 0; i < 4; i++)
        out[(size_t)(ty + i * 8) * Tz + t0 + tx] = tile[tx][ty + i * 8];
}

// ---------------- cp.async + ldmatrix fp16 GEMM ----------------
// A: half row-major [row][k]; B: packed uint32 [k2][n]
// MODE 0: QKV (scatter fp32 + bias)  MODE 1: output ((acc+bias)*gamma)
// MODE 2: scores (*0.125, fp32 S)    MODE 3: PV (half out)
template <int MODE, int TN, int KD, int LDA, int LDBW>
__global__ __launch_bounds__(256, 2) void gemm_h(
    const __half* __restrict__ A0,
    const unsigned* __restrict__ B0, const unsigned* __restrict__ B1, const unsigned* __restrict__ B2,
    const float* __restrict__ bias0, const float* __restrict__ bias1, const float* __restrict__ bias2,
    float* __restrict__ O0, float* __restrict__ O1, float* __restrict__ O2,
    const float* __restrict__ gamma)
{
    constexpr int PBW = TN + 8;          // B smem row stride (words), conflict-free
    constexpr int ASTW = 128 * 20;       // A stage words (128 rows x 20 words = 80B rows)
    constexpr int BSTW = 16 * PBW;
    constexpr int PANELS = KD / 32;
    constexpr int STAGES = 4;
    constexpr int WNT = TN / 4;
    constexpr int NT = WNT / 8;
    constexpr int NCH = (TN == 128) ? 2 : 1;

    extern __shared__ unsigned sh[];
    unsigned* BshW = sh + STAGES * ASTW;
    unsigned ash_s = (unsigned)__cvta_generic_to_shared(sh);
    unsigned bsh_s = (unsigned)__cvta_generic_to_shared(BshW);

    int tid = threadIdx.x;
    int lane = tid & 31, wid = tid >> 5;
    int wm = wid >> 2, wn = wid & 3;
    int r = lane >> 2, c = lane & 3;
    int z = blockIdx.z;
    int bm = blockIdx.y * 128;
    int bnL = blockIdx.x * TN;

    const __half* Ab = A0;
    const unsigned* Bb = B0;
    const float* bias = bias0;
    float* Out = O0;
    int bn = bnL;
    if constexpr (MODE == 0) {
        int which = bnL >> 10;
        bn = bnL & 1023;
        Bb   = which == 0 ? B0 : (which == 1 ? B1 : B2);
        bias = which == 0 ? bias0 : (which == 1 ? bias1 : bias2);
        Out  = which == 0 ? O0 : (which == 1 ? O1 : O2);
    } else if constexpr (MODE == 2) {
        Ab = A0 + (size_t)z * Tz * HSz;
        Bb = B0 + (size_t)z * (HSz / 2) * Tz;
    } else if constexpr (MODE == 3) {
        Ab = A0 + (size_t)z * Tz * Tz;
        Bb = B0 + (size_t)z * (Tz / 2) * HSz;
    }

    auto issue = [&](int p) {
        int st = p & (STAGES - 1);
        unsigned ab = ash_s + st * ASTW * 4;
#pragma unroll
        for (int j = 0; j < 2; j++) {
            int idx = tid + j * 256;
            int row = idx >> 2, kq = idx & 3;
            cpa16(ab + (unsigned)(row * 20 + kq * 4) * 4,
                  Ab + (size_t)(bm + row) * LDA + p * 32 + kq * 8);
        }
        unsigned bb = bsh_s + st * BSTW * 4;
#pragma unroll
        for (int j = 0; j < NCH; j++) {
            int idx = tid + j * 256;
            int k2r = (TN == 128) ? (idx >> 5) : (idx >> 4);
            int nc  = (idx & (TN / 4 - 1)) * 4;
            cpa16(bb + (unsigned)(k2r * PBW + nc) * 4,
                  Bb + (size_t)(p * 16 + k2r) * LDBW + bn + nc);
        }
    };

    float acc[4][NT][4];
#pragma unroll
    for (int mi = 0; mi < 4; mi++)
#pragma unroll
        for (int ni = 0; ni < NT; ni++)
#pragma unroll
            for (int l = 0; l < 4; l++) acc[mi][ni][l] = 0.f;

#pragma unroll
    for (int s = 0; s < 3; s++) {
        if (s < PANELS) issue(s);
        cpcommit();
    }

    int lrow = lane & 15;
    int lk = (lane >> 4) & 1;

    for (int p = 0; p < PANELS; p++) {
        asm volatile("cp.async.wait_group 2;");
        __syncthreads();
        int st = p & (STAGES - 1);
        const unsigned* Bs = BshW + st * BSTW;
        unsigned abase = ash_s + st * ASTW * 4;
#pragma unroll
        for (int ks = 0; ks < 2; ks++) {
            unsigned af[4][4];
#pragma unroll
            for (int mi = 0; mi < 4; mi++) {
                int row = wm * 64 + mi * 16 + lrow;
                unsigned addr = abase + (unsigned)(row * 80 + (ks * 16 + lk * 8) * 2);
                asm volatile(
                    "ldmatrix.sync.aligned.m8n8.x4.shared.b16 {%0,%1,%2,%3},[%4];"
                    : "=r"(af[mi][0]), "=r"(af[mi][1]),
                      "=r"(af[mi][2]), "=r"(af[mi][3])
                    : "r"(addr));
            }
            unsigned bf[NT][2];
#pragma unroll
            for (int ni = 0; ni < NT; ni++) {
                int cb = wn * WNT + ni * 8 + r;
                bf[ni][0] = Bs[(ks * 8 + c) * PBW + cb];
                bf[ni][1] = Bs[(ks * 8 + c + 4) * PBW + cb];
            }
#pragma unroll
            for (int mi = 0; mi < 4; mi++)
#pragma unroll
                for (int ni = 0; ni < NT; ni++)
                    asm volatile(
                        "mma.sync.aligned.m16n8k16.row.col.f32.f16.f16.f32 "
                        "{%0,%1,%2,%3},{%4,%5,%6,%7},{%8,%9},{%0,%1,%2,%3};"
                        : "+f"(acc[mi][ni][0]), "+f"(acc[mi][ni][1]),
                          "+f"(acc[mi][ni][2]), "+f"(acc[mi][ni][3])
                        : "r"(af[mi][0]), "r"(af[mi][1]),
                          "r"(af[mi][2]), "r"(af[mi][3]),
                          "r"(bf[ni][0]), "r"(bf[ni][1]));
        }
        if (p + 3 < PANELS) issue(p + 3);
        cpcommit();
    }

#pragma unroll
    for (int mi = 0; mi < 4; mi++) {
#pragma unroll
        for (int ni = 0; ni < NT; ni++) {
#pragma unroll
            for (int half = 0; half < 2; half++) {
                int row = bm + wm * 64 + mi * 16 + r + half * 8;
                int colt = bn + wn * WNT + ni * 8 + c * 2;
                float v0 = acc[mi][ni][half * 2 + 0];
                float v1 = acc[mi][ni][half * 2 + 1];
                if constexpr (MODE == 0) {
                    int b = row >> 10, t = row & 1023;
                    int h = colt >> 6, d = colt & 63;
                    float2 o = make_float2(v0 + bias[colt], v1 + bias[colt + 1]);
                    *(float2*)(Out + ((((size_t)b * Hz + h) * Tz + t) * HSz + d)) = o;
                } else if constexpr (MODE == 1) {
                    int t = row & 1023;
                    float gm = gamma[t];
                    float2 o = make_float2((v0 + bias[colt]) * gm,
                                           (v1 + bias[colt + 1]) * gm);
                    *(float2*)(Out + (size_t)row * Cz + colt) = o;
                } else if constexpr (MODE == 2) {
                    float2 o = make_float2(v0 * 0.125f, v1 * 0.125f);
                    *(float2*)(Out + (size_t)z * Tz * Tz + (size_t)row * Tz + colt) = o;
                } else {
                    int b = z >> 4, g = z & 15;
                    unsigned* yw = (unsigned*)Out;
                    size_t hidx = ((size_t)b * Tz + row) * Cz + g * HSz + colt;
                    yw[hidx >> 1] = packh2(v0, v1);
                }
            }
        }
    }
}

// ---------------- softmax + w + head-mix (fused), M2 half out -----------------
__global__ __launch_bounds__(512) void softmax_mix(
    const float* __restrict__ S, unsigned* __restrict__ M2w,
    const float* __restrict__ tw, const float* __restrict__ alpha,
    const float* __restrict__ beta, const float* __restrict__ Wmix)
{
    extern __shared__ float sm[];
    const int PR = 1026;
    float* P = sm;
    float* wmix = sm + 16 * PR;
    int t = blockIdx.x, b = blockIdx.y;
    int tid = threadIdx.x, lane = tid & 31, h = tid >> 5;

    if (tid < 256) wmix[tid] = Wmix[tid];

    const float4* row = (const float4*)(S + (((size_t)b * Hz + h) * Tz + t) * Tz);
    float4 v[8];
    float mx = -1e30f;
#pragma unroll
    for (int j = 0; j < 8; j++) {
        v[j] = row[lane + j * 32];
        mx = fmaxf(mx, fmaxf(fmaxf(v[j].x, v[j].y), fmaxf(v[j].z, v[j].w)));
    }
#pragma unroll
    for (int o = 16; o; o >>= 1) mx = fmaxf(mx, __shfl_xor_sync(~0u, mx, o));
    float sum = 0.f;
#pragma unroll
    for (int j = 0; j < 8; j++) {
        v[j].x = __expf(v[j].x - mx); v[j].y = __expf(v[j].y - mx);
        v[j].z = __expf(v[j].z - mx); v[j].w = __expf(v[j].w - mx);
        sum += v[j].x + v[j].y + v[j].z + v[j].w;
    }
#pragma unroll
    for (int o = 16; o; o >>= 1) sum += __shfl_xor_sync(~0u, sum, o);
    float bt = beta[h * Tz + t] / sum;
#pragma unroll
    for (int j = 0; j < 8; j++) {
        int s0 = (lane + j * 32) * 4;
        float* vf = (float*)&v[j];
#pragma unroll
        for (int l = 0; l < 4; l++) {
            int s = s0 + l;
            float w = 0.f;
            if (s <= t) w = tw[h * Tz + 1023 + s - t] * alpha[h * Tz + s] * bt;
            P[h * PR + s] = vf[l] * w;
        }
    }
    __syncthreads();
    {
        int s2 = tid;
        float2 p2[16];
#pragma unroll
        for (int hh = 0; hh < 16; hh++)
            p2[hh] = *(float2*)&P[hh * PR + 2 * s2];
#pragma unroll
        for (int g = 0; g < 16; g++) {
            float a0 = 0.f, a1 = 0.f;
#pragma unroll
            for (int hh = 0; hh < 16; hh++) {
                float wv = wmix[g * 16 + hh];
                a0 = fmaf(wv, p2[hh].x, a0);
                a1 = fmaf(wv, p2[hh].y, a1);
            }
            M2w[(((size_t)b * Hz + g) * Tz + t) * (Tz / 2) + s2] = packh2(a0, a1);
        }
    }
}

// ---------------- launch ----------------
extern "C" void kernel_launch(void* const* d_in, const int* in_sizes, int n_in,
                              void* d_out, int out_size) {
    const float* x          = (const float*)d_in[0];
    const float* time_w     = (const float*)d_in[1];
    const float* time_alpha = (const float*)d_in[2];
    const float* time_beta  = (const float*)d_in[3];
    const float* time_gamma = (const float*)d_in[4];
    const float* Wq = (const float*)d_in[5];
    const float* bq = (const float*)d_in[6];
    const float* Wk = (const float*)d_in[7];
    const float* bk = (const float*)d_in[8];
    const float* Wv = (const float*)d_in[9];
    const float* bv = (const float*)d_in[10];
    const float* Wmix = (const float*)d_in[11];
    const float* Wo = (const float*)d_in[12];
    const float* bo = (const float*)d_in[13];
    float* out = (float*)d_out;

    __half *xsh, *qh, *kh, *yh, *M2;
    unsigned *Wqp, *Wkp, *Wvp, *Wop, *ktp, *vp;
    float *q, *k, *v, *S;
    cudaGetSymbolAddress((void**)&xsh, g_xsh);
    cudaGetSymbolAddress((void**)&Wqp, g_Wqp);
    cudaGetSymbolAddress((void**)&Wkp, g_Wkp);
    cudaGetSymbolAddress((void**)&Wvp, g_Wvp);
    cudaGetSymbolAddress((void**)&Wop, g_Wop);
    cudaGetSymbolAddress((void**)&q,  g_q);
    cudaGetSymbolAddress((void**)&k,  g_k);
    cudaGetSymbolAddress((void**)&v,  g_v);
    cudaGetSymbolAddress((void**)&qh, g_qh);
    cudaGetSymbolAddress((void**)&kh, g_kh);
    cudaGetSymbolAddress((void**)&ktp, g_ktp);
    cudaGetSymbolAddress((void**)&vp, g_vp);
    cudaGetSymbolAddress((void**)&S,  g_S);
    cudaGetSymbolAddress((void**)&M2, g_M2);
    cudaGetSymbolAddress((void**)&yh, g_yh);

    constexpr int SM128 = (4 * 128 * 20 + 4 * 16 * 136) * 4;   // 75776
    constexpr int SM64  = (4 * 128 * 20 + 4 * 16 * 72) * 4;    // 59392
    constexpr int SMX = (16 * 1026 + 256) * 4;

    cudaFuncSetAttribute((const void*)gemm_h<0, 128, 1024, 1024, 1024>,
                         cudaFuncAttributeMaxDynamicSharedMemorySize, SM128);
    cudaFuncSetAttribute((const void*)gemm_h<1, 128, 1024, 1024, 1024>,
                         cudaFuncAttributeMaxDynamicSharedMemorySize, SM128);
    cudaFuncSetAttribute((const void*)gemm_h<2, 128, 64, 64, 1024>,
                         cudaFuncAttributeMaxDynamicSharedMemorySize, SM128);
    cudaFuncSetAttribute((const void*)gemm_h<3, 64, 1024, 1024, 64>,
                         cudaFuncAttributeMaxDynamicSharedMemorySize, SM64);
    cudaFuncSetAttribute((const void*)softmax_mix,
                         cudaFuncAttributeMaxDynamicSharedMemorySize, SMX);

    shift_cvt<<<(Bz * Tz * Cz / 2) / 256, 256>>>(x, xsh);
    wpack<<<1024, 512>>>(Wq, Wqp);
    wpack<<<1024, 512>>>(Wk, Wkp);
    wpack<<<1024, 512>>>(Wv, Wvp);
    wpack<<<1024, 512>>>(Wo, Wop);

    gemm_h<0, 128, 1024, 1024, 1024><<<dim3(24, 16, 1), 256, SM128>>>(
        xsh, Wqp, Wkp, Wvp, bq, bk, bv, q, k, v, nullptr);

    rope_cvt<<<(Bz * Hz * Tz * 16) / 256, 256>>>(q, k, qh, kh);
    ktrans32<<<dim3(32, Bz * Hz), 256>>>(kh, ktp);
    vpack<<<(Bz * Hz * (Tz / 2) * HSz) / 256, 256>>>(v, vp);

    gemm_h<2, 128, 64, 64, 1024><<<dim3(8, 8, Bz * Hz), 256, SM128>>>(
        qh, ktp, nullptr, nullptr, nullptr, nullptr, nullptr, S, nullptr, nullptr, nullptr);

    softmax_mix<<<dim3(Tz, Bz), 512, SMX>>>(S, (unsigned*)M2, time_w, time_alpha,
                                            time_beta, Wmix);

    gemm_h<3, 64, 1024, 1024, 64><<<dim3(1, 8, Bz * Hz), 256, SM64>>>(
        M2, vp, nullptr, nullptr, nullptr, nullptr, nullptr, (float*)yh, nullptr, nullptr, nullptr);

    gemm_h<1, 128, 1024, 1024, 1024><<<dim3(8, 16, 1), 256, SM128>>>(
        yh, Wop, nullptr, nullptr, bo, nullptr, nullptr, out, nullptr, nullptr, time_gamma);
}